// round 6
// baseline (speedup 1.0000x reference)
#include <cuda_runtime.h>
#include <cuda_fp16.h>
#include <cstdint>

// ============================================================================
// Upsample: out = stack_k(x @ W[k]) [8*65536,128] -> BN(train stats) -> ReLU
// fp16 mma.sync GEMM, analytic BN stats (colsum + Gram), fused BN+ReLU.
// R6: f16-accumulated MMA (2 chains of K=128, promoted in epilogue) for 2x
// HMMA rate; gram_k 3-stage cp.async pipeline with wait_group 1.
// ============================================================================

#define MT      65536
#define KT      256
#define CO      128
#define NOFF    8
#define BM      128
#define MTILES  512
#define GSPLIT  64            // k-splits for Gram (1024 rows each)

// ---- device scratch ----
__device__ __align__(16) __half g_xh[(size_t)MT * KT];        // row-major
__device__ __align__(16) __half g_xt[(size_t)KT * MT];        // transposed
__device__ __align__(16) __half g_wh[NOFF * CO * KT];         // [k][n][kk]
__device__ float g_gp[(size_t)GSPLIT * KT * KT];              // Gram partials
__device__ float g_G [KT * KT];
__device__ float g_cs[KT];
__device__ float g_scale[CO];
__device__ float g_bias [CO];

// ---- PTX helpers ----
__device__ __forceinline__ uint32_t smem_u32(const void* p) {
    uint32_t a;
    asm("{ .reg .u64 t; cvta.to.shared.u64 t, %1; cvt.u32.u64 %0, t; }" : "=r"(a) : "l"(p));
    return a;
}
__device__ __forceinline__ void cp16(uint32_t dst, const void* src) {
    asm volatile("cp.async.cg.shared.global [%0], [%1], 16;" :: "r"(dst), "l"(src) : "memory");
}
#define CP_COMMIT() asm volatile("cp.async.commit_group;" ::: "memory")
#define CP_WAIT(n)  asm volatile("cp.async.wait_group %0;" :: "n"(n) : "memory")

__device__ __forceinline__ void ldsm4(uint32_t r[4], uint32_t a) {
    asm volatile("ldmatrix.sync.aligned.m8n8.x4.shared.b16 {%0,%1,%2,%3}, [%4];"
                 : "=r"(r[0]), "=r"(r[1]), "=r"(r[2]), "=r"(r[3]) : "r"(a));
}
// f32-accum (Gram path: feeds variance, keep full accuracy)
__device__ __forceinline__ void mma16816(float d[4], const uint32_t a[4], const uint32_t b[2]) {
    asm volatile(
        "mma.sync.aligned.m16n8k16.row.col.f32.f16.f16.f32 "
        "{%0,%1,%2,%3}, {%4,%5,%6,%7}, {%8,%9}, {%0,%1,%2,%3};"
        : "+f"(d[0]), "+f"(d[1]), "+f"(d[2]), "+f"(d[3])
        : "r"(a[0]), "r"(a[1]), "r"(a[2]), "r"(a[3]), "r"(b[0]), "r"(b[1]));
}
// f16-accum (main GEMM: 2x HMMA rate)
__device__ __forceinline__ void mma16816h(uint32_t d[2], const uint32_t a[4], const uint32_t b[2]) {
    asm volatile(
        "mma.sync.aligned.m16n8k16.row.col.f16.f16.f16.f16 "
        "{%0,%1}, {%2,%3,%4,%5}, {%6,%7}, {%0,%1};"
        : "+r"(d[0]), "+r"(d[1])
        : "r"(a[0]), "r"(a[1]), "r"(a[2]), "r"(a[3]), "r"(b[0]), "r"(b[1]));
}

// ============================================================================
// prep: x -> fp16 row-major + transposed (vectorized), W -> fp16 k-contig
// ============================================================================
__global__ __launch_bounds__(256) void convert_x(const float* __restrict__ x) {
    __shared__ __half tile[64 * 65];
    const int tid = threadIdx.x;
    const int r0 = blockIdx.x * 64, c0 = blockIdx.y * 64;
#pragma unroll
    for (int h = 0; h < 2; h++) {
        int rl = h * 32 + (tid >> 3), cl = (tid & 7) * 8;
        const float* src = x + (size_t)(r0 + rl) * KT + c0 + cl;
        float4 f0 = *(const float4*)src;
        float4 f1 = *(const float4*)(src + 4);
        float v[8] = {f0.x, f0.y, f0.z, f0.w, f1.x, f1.y, f1.z, f1.w};
        __half hh[8];
#pragma unroll
        for (int j = 0; j < 8; j++) hh[j] = __float2half(v[j]);
        *(uint4*)(g_xh + (size_t)(r0 + rl) * KT + c0 + cl) = *(uint4*)hh;
#pragma unroll
        for (int j = 0; j < 8; j++) tile[rl * 65 + cl + j] = hh[j];
    }
    __syncthreads();
#pragma unroll
    for (int h = 0; h < 2; h++) {
        int cl = h * 32 + (tid >> 3), rl = (tid & 7) * 8;
        __half t[8];
#pragma unroll
        for (int j = 0; j < 8; j++) t[j] = tile[(rl + j) * 65 + cl];
        *(uint4*)(g_xt + (size_t)(c0 + cl) * MT + r0 + rl) = *(uint4*)t;
    }
}

__global__ __launch_bounds__(256) void convert_w(const float* __restrict__ W) {
    int b = blockIdx.x;              // k*128 + n
    int k = b >> 7, n = b & 127;
    int kk = threadIdx.x;
    g_wh[(size_t)b * KT + kk] = __float2half(W[((size_t)(k * KT + kk)) * CO + n]);
}

// ============================================================================
// colsum(x) per channel (deterministic)
// ============================================================================
__global__ __launch_bounds__(256) void colsum_k() {
    const int ch = blockIdx.x, t = threadIdx.x;
    const uint4* p = (const uint4*)(g_xt + (size_t)ch * MT + (size_t)t * 256);
    float s = 0.f;
#pragma unroll 4
    for (int i = 0; i < 32; i++) {
        uint4 u = p[i];
        const __half2* h2 = (const __half2*)&u;
#pragma unroll
        for (int j = 0; j < 4; j++) { float2 f = __half22float2(h2[j]); s += f.x + f.y; }
    }
    __shared__ float sm[256];
    sm[t] = s; __syncthreads();
    for (int st = 128; st > 0; st >>= 1) {
        if (t < st) sm[t] += sm[t + st];
        __syncthreads();
    }
    if (t == 0) g_cs[ch] = sm[0];
}

// ============================================================================
// Gram partials: grid (GSPLIT, 4). 3-stage XOR-swizzled pipeline, wait(1).
// Warps 4x2, warp tile 64x32, f32 accumulation.
// ============================================================================
#define GR_STAGE 32768      // 256 ch x 128B (XOR swizzled, 64 halves/row)
__global__ __launch_bounds__(256, 2) void gram_k()
{
    extern __shared__ char smem[];
    const uint32_t sb = smem_u32(smem);
    const int tid = threadIdx.x, lane = tid & 31, w = tid >> 5;
    const int wm = w & 3, wn = w >> 2;          // 4 x 2
    const int cta = blockIdx.x, jh = blockIdx.y;
    const size_t kbase = (size_t)cta * 1024;

    auto load_t = [&](int ch) {
        uint32_t dst = sb + (uint32_t)((ch % 3) * GR_STAGE);
        size_t k0 = kbase + (size_t)ch * 64;
        for (int i = tid; i < 2048; i += 256) {
            int n = i >> 3, kb = i & 7;
            cp16(dst + n * 128 + (uint32_t)((kb ^ (n & 7)) << 4),
                 g_xt + (size_t)n * MT + k0 + kb * 8);
        }
        CP_COMMIT();
    };
    load_t(0);
    load_t(1);

    float c[4][4][4];
#pragma unroll
    for (int a = 0; a < 4; a++)
#pragma unroll
        for (int b = 0; b < 4; b++)
#pragma unroll
            for (int e = 0; e < 4; e++) c[a][b][e] = 0.f;

    const int lrow = lane & 15, lcb = lane >> 4, xm = lane & 7;
    const uint32_t aRow = sb + (wm * 64 + lrow) * 128;
    const uint32_t bRow = sb + (jh * 64 + wn * 32 + lrow) * 128;

    for (int ch = 0; ch < 16; ch++) {
        if (ch < 15) { CP_WAIT(1); } else { CP_WAIT(0); }
        __syncthreads();
        if (ch + 2 < 16) load_t(ch + 2);
        const uint32_t off = (uint32_t)((ch % 3) * GR_STAGE);
#pragma unroll
        for (int ks = 0; ks < 4; ks++) {
            const uint32_t u = (uint32_t)(((ks * 2 + lcb) ^ xm) << 4);
            uint32_t af[4][4];
#pragma unroll
            for (int mf = 0; mf < 4; mf++) ldsm4(af[mf], aRow + off + mf * 16 * 128 + u);
            uint32_t bf[4][2];
#pragma unroll
            for (int p = 0; p < 2; p++) {
                uint32_t r[4];
                ldsm4(r, bRow + off + p * 16 * 128 + u);
                bf[2 * p][0] = r[0]; bf[2 * p][1] = r[2];
                bf[2 * p + 1][0] = r[1]; bf[2 * p + 1][1] = r[3];
            }
#pragma unroll
            for (int mf = 0; mf < 4; mf++)
#pragma unroll
                for (int nt = 0; nt < 4; nt++) mma16816(c[mf][nt], af[mf], bf[nt]);
        }
    }

    float* dst = g_gp + (size_t)cta * (KT * KT);
#pragma unroll
    for (int mf = 0; mf < 4; mf++)
#pragma unroll
        for (int nt = 0; nt < 4; nt++) {
            int i0 = wm * 64 + mf * 16 + (lane >> 2);
            int j0 = jh * 64 + wn * 32 + nt * 8 + (lane & 3) * 2;
            *(float2*)(dst + (size_t)i0 * KT + j0) = make_float2(c[mf][nt][0], c[mf][nt][1]);
            *(float2*)(dst + (size_t)(i0 + 8) * KT + j0) = make_float2(c[mf][nt][2], c[mf][nt][3]);
        }
}

__global__ __launch_bounds__(256) void gram_reduce() {
    const int i = blockIdx.x, j = threadIdx.x;
    float s = 0.f;
    const float* p = g_gp + (size_t)i * KT + j;
    for (int q = 0; q < GSPLIT; q++) s += p[(size_t)q * (KT * KT)];
    g_G[i * KT + j] = s;
}

// ============================================================================
// stats: mean = cs.(sum_k W_k[:,d])/(8N); E[o^2] = sum_k w^T G w /(8N)
// ============================================================================
__global__ __launch_bounds__(256) void stats_k(const float* __restrict__ W,
                                               const float* __restrict__ gamma,
                                               const float* __restrict__ beta)
{
    const int d = blockIdx.x, j = threadIdx.x;
    __shared__ float Ws[NOFF][KT];
    __shared__ float red[256];
#pragma unroll
    for (int k = 0; k < NOFF; k++)
        Ws[k][j] = W[((size_t)k * KT + j) * CO + d];
    __syncthreads();

    float inner[NOFF];
#pragma unroll
    for (int k = 0; k < NOFF; k++) inner[k] = 0.f;
    for (int i = 0; i < KT; i++) {
        float g = g_G[i * KT + j];
#pragma unroll
        for (int k = 0; k < NOFF; k++) inner[k] = fmaf(g, Ws[k][i], inner[k]);
    }
    float qj = 0.f, mj = 0.f;
    const float csj = g_cs[j];
#pragma unroll
    for (int k = 0; k < NOFF; k++) {
        qj = fmaf(inner[k], Ws[k][j], qj);
        mj = fmaf(csj, Ws[k][j], mj);
    }
    red[j] = qj; __syncthreads();
    for (int st = 128; st > 0; st >>= 1) { if (j < st) red[j] += red[j + st]; __syncthreads(); }
    float qtot = red[0]; __syncthreads();
    red[j] = mj; __syncthreads();
    for (int st = 128; st > 0; st >>= 1) { if (j < st) red[j] += red[j + st]; __syncthreads(); }
    if (j == 0) {
        const float invN = 1.f / (float)((size_t)NOFF * MT);
        float mean = red[0] * invN;
        float var  = qtot * invN - mean * mean;
        float sc   = gamma[d] * rsqrtf(var + 1e-5f);
        g_scale[d] = sc;
        g_bias[d]  = beta[d] - mean * sc;
    }
}

// ============================================================================
// main GEMM: f16-accumulated mma (2 chains of K=128), fused BN+ReLU epilogue.
// ============================================================================
#define O_A     0
#define A_BYTES 65536                  // 128 rows x 512B (XOR swizzled)
#define O_B     A_BYTES
#define B_STAGE 16384                  // 128 n x 128B (XOR swizzled)
#define O_SC    (O_B + 2 * B_STAGE)    // 98304
#define SMEM_G  (O_SC + 1024)          // 99328

__global__ __launch_bounds__(256, 2) void gemm_mma(float* __restrict__ out)
{
    extern __shared__ char smem[];
    const uint32_t sb = smem_u32(smem);
    const int tid = threadIdx.x, lane = tid & 31, w = tid >> 5;
    const int wm = w & 3, wn = w >> 2;          // 4 x 2 warp grid
    const int bx = blockIdx.x;

    float* scs = (float*)(smem + O_SC);
    float* bis = scs + CO;
    if (tid < CO) { scs[tid] = g_scale[tid]; bis[tid] = g_bias[tid]; }

    // A tile via cp.async (XOR swizzle): 128 rows x 32 x 16B
    {
        const __half* base = g_xh + (size_t)bx * BM * KT;
        for (int i = tid; i < 4096; i += 256) {
            int m = i >> 5, u = i & 31;
            uint32_t up = (uint32_t)((u & 24) | ((u ^ m) & 7));
            cp16(sb + O_A + m * 512 + (up << 4), base + (size_t)m * KT + u * 8);
        }
        CP_COMMIT();
    }

    auto load_b = [&](int it) {
        int ko = it >> 2, c = it & 3, st = it & 1;
        const __half* wb = g_wh + (size_t)ko * CO * KT;
        uint32_t dstb = sb + O_B + st * B_STAGE;
        for (int i = tid; i < 1024; i += 256) {
            int n = i >> 3, kb = i & 7;
            cp16(dstb + n * 128 + (uint32_t)((kb ^ (n & 7)) << 4),
                 wb + (size_t)n * KT + c * 64 + kb * 8);
        }
        CP_COMMIT();
    };
    load_b(0);

    // f16 accumulators: [chain(K half)][mt][nt][2 regs] = 64 regs
    uint32_t ch16[2][2][8][2];
#pragma unroll
    for (int q = 0; q < 2; q++)
#pragma unroll
        for (int mt = 0; mt < 2; mt++)
#pragma unroll
            for (int nt = 0; nt < 8; nt++) { ch16[q][mt][nt][0] = 0u; ch16[q][mt][nt][1] = 0u; }

    const int lrow = lane & 15, lcb = lane >> 4, xm = lane & 7;
    const uint32_t aRow  = sb + O_A + (wm * 32 + lrow) * 512;
    const uint32_t aRow2 = aRow + 16 * 512;
    const uint32_t bRow  = sb + O_B + (wn * 64 + lrow) * 128;

    for (int it = 0; it < 32; it++) {
        CP_WAIT(0);
        __syncthreads();
        if (it + 1 < 32) load_b(it + 1);

        const int st = it & 1, cch = it & 3, ko = it >> 2, q = cch >> 1;
        const uint32_t stageOff = (uint32_t)(st * B_STAGE);

#pragma unroll
        for (int ks = 0; ks < 4; ks++) {
            const uint32_t xr = (uint32_t)((ks * 2 + lcb) ^ xm);
            const uint32_t au = (uint32_t)((cch * 8) << 4) + (xr << 4);
            const uint32_t bu = (xr << 4);
            uint32_t a0[4], a1[4];
            ldsm4(a0, aRow + au);
            ldsm4(a1, aRow2 + au);
            uint32_t bfr[8][2];
#pragma unroll
            for (int p = 0; p < 4; p++) {
                uint32_t r[4];
                ldsm4(r, bRow + stageOff + p * 16 * 128 + bu);
                bfr[2 * p][0] = r[0]; bfr[2 * p][1] = r[2];
                bfr[2 * p + 1][0] = r[1]; bfr[2 * p + 1][1] = r[3];
            }
#pragma unroll
            for (int nt = 0; nt < 8; nt++) {
                mma16816h(ch16[q][0][nt], a0, bfr[nt]);
                mma16816h(ch16[q][1][nt], a1, bfr[nt]);
            }
        }

        if (cch == 3) {  // offset ko complete: promote + fused BN + ReLU
            const size_t rbase = (size_t)ko * MT + (size_t)bx * BM + wm * 32 + (lane >> 2);
            const int colb = wn * 64 + (lane & 3) * 2;
#pragma unroll
            for (int nt = 0; nt < 8; nt++) {
                const int ch0 = colb + nt * 8;
                const float s0 = scs[ch0], s1 = scs[ch0 + 1];
                const float b0 = bis[ch0], b1 = bis[ch0 + 1];
#pragma unroll
                for (int mt = 0; mt < 2; mt++) {
#pragma unroll
                    for (int part = 0; part < 2; part++) {
                        float2 fA = __half22float2(*(__half2*)&ch16[0][mt][nt][part]);
                        float2 fB = __half22float2(*(__half2*)&ch16[1][mt][nt][part]);
                        float y0 = fmaxf(fmaf(fA.x + fB.x, s0, b0), 0.f);
                        float y1 = fmaxf(fmaf(fA.y + fB.y, s1, b1), 0.f);
                        float* p0 = out + (rbase + mt * 16 + part * 8) * CO + ch0;
                        *(float2*)p0 = make_float2(y0, y1);
                    }
                }
            }
#pragma unroll
            for (int qq = 0; qq < 2; qq++)
#pragma unroll
                for (int mt = 0; mt < 2; mt++)
#pragma unroll
                    for (int nt = 0; nt < 8; nt++) {
                        ch16[qq][mt][nt][0] = 0u; ch16[qq][mt][nt][1] = 0u;
                    }
        }
    }
}

// ============================================================================
extern "C" void kernel_launch(void* const* d_in, const int* in_sizes, int n_in,
                              void* d_out, int out_size)
{
    const float* x     = (const float*)d_in[0];   // [65536,256]
    const float* W     = (const float*)d_in[1];   // [8,256,128]
    const float* gamma = (const float*)d_in[2];
    const float* beta  = (const float*)d_in[3];
    float* out = (float*)d_out;

    cudaFuncSetAttribute(gram_k,   cudaFuncAttributeMaxDynamicSharedMemorySize, 3 * GR_STAGE);
    cudaFuncSetAttribute(gemm_mma, cudaFuncAttributeMaxDynamicSharedMemorySize, SMEM_G);

    dim3 cgrid(MT / 64, KT / 64);
    convert_x<<<cgrid, 256>>>(x);
    convert_w<<<NOFF * CO, 256>>>(W);
    colsum_k<<<KT, 256>>>();
    dim3 ggrid(GSPLIT, 4);
    gram_k<<<ggrid, 256, 3 * GR_STAGE>>>();
    gram_reduce<<<KT, 256>>>();
    stats_k<<<CO, 256>>>(W, gamma, beta);
    gemm_mma<<<MTILES, 256, SMEM_G>>>(out);
}

// round 8
// speedup vs baseline: 1.3801x; 1.3801x over previous
#include <cuda_runtime.h>
#include <cuda_fp16.h>
#include <cstdint>

// ============================================================================
// Upsample: out = stack_k(x @ W[k]) [8*65536,128] -> BN(train stats) -> ReLU
// fp16 mma.sync (f32 accum) GEMM, analytic BN stats (colsum + Gram), fused
// BN+ReLU epilogue. R8 = R7 resubmit (prior run died to a container init
// flake before launch): colsum fused into convert_x; gemm 3-stage cp.async
// B pipeline (wait_group 1).
// ============================================================================

#define MT      65536
#define KT      256
#define CO      128
#define NOFF    8
#define BM      128
#define MTILES  512
#define GSPLIT  64            // k-splits for Gram (1024 rows each)
#define MBLK    (MT / 64)     // 1024 convert blocks along M

// ---- device scratch ----
__device__ __align__(16) __half g_xh[(size_t)MT * KT];        // row-major
__device__ __align__(16) __half g_xt[(size_t)KT * MT];        // transposed
__device__ __align__(16) __half g_wh[NOFF * CO * KT];         // [k][n][kk]
__device__ float g_gp[(size_t)GSPLIT * KT * KT];              // Gram partials
__device__ float g_G [KT * KT];
__device__ float g_cspart[KT * MBLK];                         // [ch][mblk]
__device__ float g_cs[KT];
__device__ float g_scale[CO];
__device__ float g_bias [CO];

// ---- PTX helpers ----
__device__ __forceinline__ uint32_t smem_u32(const void* p) {
    uint32_t a;
    asm("{ .reg .u64 t; cvta.to.shared.u64 t, %1; cvt.u32.u64 %0, t; }" : "=r"(a) : "l"(p));
    return a;
}
__device__ __forceinline__ void cp16(uint32_t dst, const void* src) {
    asm volatile("cp.async.cg.shared.global [%0], [%1], 16;" :: "r"(dst), "l"(src) : "memory");
}
#define CP_COMMIT() asm volatile("cp.async.commit_group;" ::: "memory")
#define CP_WAIT(n)  asm volatile("cp.async.wait_group %0;" :: "n"(n) : "memory")

__device__ __forceinline__ void ldsm4(uint32_t r[4], uint32_t a) {
    asm volatile("ldmatrix.sync.aligned.m8n8.x4.shared.b16 {%0,%1,%2,%3}, [%4];"
                 : "=r"(r[0]), "=r"(r[1]), "=r"(r[2]), "=r"(r[3]) : "r"(a));
}
__device__ __forceinline__ void mma16816(float d[4], const uint32_t a[4], const uint32_t b[2]) {
    asm volatile(
        "mma.sync.aligned.m16n8k16.row.col.f32.f16.f16.f32 "
        "{%0,%1,%2,%3}, {%4,%5,%6,%7}, {%8,%9}, {%0,%1,%2,%3};"
        : "+f"(d[0]), "+f"(d[1]), "+f"(d[2]), "+f"(d[3])
        : "r"(a[0]), "r"(a[1]), "r"(a[2]), "r"(a[3]), "r"(b[0]), "r"(b[1]));
}

// ============================================================================
// prep: x -> fp16 row-major + transposed + per-Mblock column partial sums
// ============================================================================
__global__ __launch_bounds__(256) void convert_x(const float* __restrict__ x) {
    __shared__ __half tile[64 * 65];
    const int tid = threadIdx.x;
    const int r0 = blockIdx.x * 64, c0 = blockIdx.y * 64;
#pragma unroll
    for (int h = 0; h < 2; h++) {
        int rl = h * 32 + (tid >> 3), cl = (tid & 7) * 8;
        const float* src = x + (size_t)(r0 + rl) * KT + c0 + cl;
        float4 f0 = *(const float4*)src;
        float4 f1 = *(const float4*)(src + 4);
        float v[8] = {f0.x, f0.y, f0.z, f0.w, f1.x, f1.y, f1.z, f1.w};
        __half hh[8];
#pragma unroll
        for (int j = 0; j < 8; j++) hh[j] = __float2half(v[j]);
        *(uint4*)(g_xh + (size_t)(r0 + rl) * KT + c0 + cl) = *(uint4*)hh;
#pragma unroll
        for (int j = 0; j < 8; j++) tile[rl * 65 + cl + j] = hh[j];
    }
    __syncthreads();
#pragma unroll
    for (int h = 0; h < 2; h++) {
        int cl = h * 32 + (tid >> 3), rl = (tid & 7) * 8;
        __half t[8];
        float s = 0.f;
#pragma unroll
        for (int j = 0; j < 8; j++) {
            t[j] = tile[(rl + j) * 65 + cl];
            s += __half2float(t[j]);
        }
        *(uint4*)(g_xt + (size_t)(c0 + cl) * MT + r0 + rl) = *(uint4*)t;
        // column partial over this block's 64 rows (width-8 shfl groups)
        s += __shfl_down_sync(0xffffffffu, s, 4, 8);
        s += __shfl_down_sync(0xffffffffu, s, 2, 8);
        s += __shfl_down_sync(0xffffffffu, s, 1, 8);
        if ((tid & 7) == 0) g_cspart[(size_t)(c0 + cl) * MBLK + blockIdx.x] = s;
    }
}

__global__ __launch_bounds__(256) void convert_w(const float* __restrict__ W) {
    int b = blockIdx.x;              // k*128 + n
    int k = b >> 7, n = b & 127;
    int kk = threadIdx.x;
    g_wh[(size_t)b * KT + kk] = __float2half(W[((size_t)(k * KT + kk)) * CO + n]);
}

__global__ __launch_bounds__(256) void cs_reduce() {
    const int ch = blockIdx.x, t = threadIdx.x;
    const float* p = g_cspart + (size_t)ch * MBLK + t * 4;
    float s = p[0] + p[1] + p[2] + p[3];
    __shared__ float sm[256];
    sm[t] = s; __syncthreads();
    for (int st = 128; st > 0; st >>= 1) {
        if (t < st) sm[t] += sm[t + st];
        __syncthreads();
    }
    if (t == 0) g_cs[ch] = sm[0];
}

// ============================================================================
// Gram partials: grid (GSPLIT, 4). 2-stage XOR-swizzled pipeline, 1 sync/iter.
// Warps 4x2, warp tile 64x32, f32 accumulation.
// ============================================================================
#define GR_STAGE 32768      // 256 ch x 128B (XOR swizzled, 64 halves/row)
__global__ __launch_bounds__(256, 2) void gram_k()
{
    extern __shared__ char smem[];
    const uint32_t sb = smem_u32(smem);
    const int tid = threadIdx.x, lane = tid & 31, w = tid >> 5;
    const int wm = w & 3, wn = w >> 2;          // 4 x 2
    const int cta = blockIdx.x, jh = blockIdx.y;
    const size_t kbase = (size_t)cta * 1024;

    auto load_t = [&](int ch) {
        uint32_t dst = sb + (uint32_t)((ch & 1) * GR_STAGE);
        size_t k0 = kbase + (size_t)ch * 64;
        for (int i = tid; i < 2048; i += 256) {
            int n = i >> 3, kb = i & 7;
            cp16(dst + n * 128 + (uint32_t)((kb ^ (n & 7)) << 4),
                 g_xt + (size_t)n * MT + k0 + kb * 8);
        }
        CP_COMMIT();
    };
    load_t(0);

    float c[4][4][4];
#pragma unroll
    for (int a = 0; a < 4; a++)
#pragma unroll
        for (int b = 0; b < 4; b++)
#pragma unroll
            for (int e = 0; e < 4; e++) c[a][b][e] = 0.f;

    const int lrow = lane & 15, lcb = lane >> 4, xm = lane & 7;
    const uint32_t aRow = sb + (wm * 64 + lrow) * 128;
    const uint32_t bRow = sb + (jh * 64 + wn * 32 + lrow) * 128;

    for (int ch = 0; ch < 16; ch++) {
        CP_WAIT(0);
        __syncthreads();
        if (ch + 1 < 16) load_t(ch + 1);
        const uint32_t off = (uint32_t)((ch & 1) * GR_STAGE);
#pragma unroll
        for (int ks = 0; ks < 4; ks++) {
            const uint32_t u = (uint32_t)(((ks * 2 + lcb) ^ xm) << 4);
            uint32_t af[4][4];
#pragma unroll
            for (int mf = 0; mf < 4; mf++) ldsm4(af[mf], aRow + off + mf * 16 * 128 + u);
            uint32_t bf[4][2];
#pragma unroll
            for (int p = 0; p < 2; p++) {
                uint32_t r[4];
                ldsm4(r, bRow + off + p * 16 * 128 + u);
                bf[2 * p][0] = r[0]; bf[2 * p][1] = r[2];
                bf[2 * p + 1][0] = r[1]; bf[2 * p + 1][1] = r[3];
            }
#pragma unroll
            for (int mf = 0; mf < 4; mf++)
#pragma unroll
                for (int nt = 0; nt < 4; nt++) mma16816(c[mf][nt], af[mf], bf[nt]);
        }
    }

    float* dst = g_gp + (size_t)cta * (KT * KT);
#pragma unroll
    for (int mf = 0; mf < 4; mf++)
#pragma unroll
        for (int nt = 0; nt < 4; nt++) {
            int i0 = wm * 64 + mf * 16 + (lane >> 2);
            int j0 = jh * 64 + wn * 32 + nt * 8 + (lane & 3) * 2;
            *(float2*)(dst + (size_t)i0 * KT + j0) = make_float2(c[mf][nt][0], c[mf][nt][1]);
            *(float2*)(dst + (size_t)(i0 + 8) * KT + j0) = make_float2(c[mf][nt][2], c[mf][nt][3]);
        }
}

__global__ __launch_bounds__(256) void gram_reduce() {
    const int i = blockIdx.x, j = threadIdx.x;
    float s = 0.f;
    const float* p = g_gp + (size_t)i * KT + j;
    for (int q = 0; q < GSPLIT; q++) s += p[(size_t)q * (KT * KT)];
    g_G[i * KT + j] = s;
}

// ============================================================================
// stats: mean = cs.(sum_k W_k[:,d])/(8N); E[o^2] = sum_k w^T G w /(8N)
// ============================================================================
__global__ __launch_bounds__(256) void stats_k(const float* __restrict__ W,
                                               const float* __restrict__ gamma,
                                               const float* __restrict__ beta)
{
    const int d = blockIdx.x, j = threadIdx.x;
    __shared__ float Ws[NOFF][KT];
    __shared__ float red[256];
#pragma unroll
    for (int k = 0; k < NOFF; k++)
        Ws[k][j] = W[((size_t)k * KT + j) * CO + d];
    __syncthreads();

    float inner[NOFF];
#pragma unroll
    for (int k = 0; k < NOFF; k++) inner[k] = 0.f;
    for (int i = 0; i < KT; i++) {
        float g = g_G[i * KT + j];
#pragma unroll
        for (int k = 0; k < NOFF; k++) inner[k] = fmaf(g, Ws[k][i], inner[k]);
    }
    float qj = 0.f, mj = 0.f;
    const float csj = g_cs[j];
#pragma unroll
    for (int k = 0; k < NOFF; k++) {
        qj = fmaf(inner[k], Ws[k][j], qj);
        mj = fmaf(csj, Ws[k][j], mj);
    }
    red[j] = qj; __syncthreads();
    for (int st = 128; st > 0; st >>= 1) { if (j < st) red[j] += red[j + st]; __syncthreads(); }
    float qtot = red[0]; __syncthreads();
    red[j] = mj; __syncthreads();
    for (int st = 128; st > 0; st >>= 1) { if (j < st) red[j] += red[j + st]; __syncthreads(); }
    if (j == 0) {
        const float invN = 1.f / (float)((size_t)NOFF * MT);
        float mean = red[0] * invN;
        float var  = qtot * invN - mean * mean;
        float sc   = gamma[d] * rsqrtf(var + 1e-5f);
        g_scale[d] = sc;
        g_bias[d]  = beta[d] - mean * sc;
    }
}

// ============================================================================
// main GEMM (fp16, f32 accum) with fused BN+ReLU epilogue.
// XOR-swizzled A (64KB resident) + 3-stage B (16KB each), wait_group 1.
// ============================================================================
#define O_A     0
#define A_BYTES 65536                  // 128 rows x 512B (XOR swizzled)
#define O_B     A_BYTES
#define B_STAGE 16384                  // 128 n x 128B (XOR swizzled)
#define SMEM_G  (O_B + 3 * B_STAGE)    // 114688

__global__ __launch_bounds__(256, 2) void gemm_mma(float* __restrict__ out)
{
    extern __shared__ char smem[];
    const uint32_t sb = smem_u32(smem);
    const int tid = threadIdx.x, lane = tid & 31, w = tid >> 5;
    const int wm = w & 3, wn = w >> 2;          // 4 x 2 warp grid
    const int bx = blockIdx.x;

    // A tile via cp.async (XOR swizzle): 128 rows x 32 x 16B
    {
        const __half* base = g_xh + (size_t)bx * BM * KT;
        for (int i = tid; i < 4096; i += 256) {
            int m = i >> 5, u = i & 31;
            uint32_t up = (uint32_t)((u & 24) | ((u ^ m) & 7));
            cp16(sb + O_A + m * 512 + (up << 4), base + (size_t)m * KT + u * 8);
        }
        CP_COMMIT();
    }

    auto load_b = [&](int it) {
        int ko = it >> 2, c = it & 3, st = it % 3;
        const __half* wb = g_wh + (size_t)ko * CO * KT;
        uint32_t dstb = sb + O_B + (uint32_t)(st * B_STAGE);
        for (int i = tid; i < 1024; i += 256) {
            int n = i >> 3, kb = i & 7;
            cp16(dstb + n * 128 + (uint32_t)((kb ^ (n & 7)) << 4),
                 wb + (size_t)n * KT + c * 64 + kb * 8);
        }
        CP_COMMIT();
    };
    load_b(0);
    load_b(1);

    float c[2][8][4];
#pragma unroll
    for (int mt = 0; mt < 2; mt++)
#pragma unroll
        for (int nt = 0; nt < 8; nt++)
#pragma unroll
            for (int e = 0; e < 4; e++) c[mt][nt][e] = 0.f;

    const int lrow = lane & 15, lcb = lane >> 4, xm = lane & 7;
    const uint32_t aRow  = sb + O_A + (wm * 32 + lrow) * 512;
    const uint32_t aRow2 = aRow + 16 * 512;
    const uint32_t bRow  = sb + O_B + (wn * 64 + lrow) * 128;

    for (int it = 0; it < 32; it++) {
        if (it < 31) { CP_WAIT(1); } else { CP_WAIT(0); }
        __syncthreads();
        if (it + 2 < 32) load_b(it + 2);

        const int cch = it & 3, ko = it >> 2;
        const uint32_t stageOff = (uint32_t)((it % 3) * B_STAGE);

#pragma unroll
        for (int ks = 0; ks < 4; ks++) {
            const uint32_t xr = (uint32_t)((ks * 2 + lcb) ^ xm);
            const uint32_t au = (uint32_t)((cch * 8) << 4) + (xr << 4);
            const uint32_t bu = (xr << 4);
            uint32_t a0[4], a1[4];
            ldsm4(a0, aRow + au);
            ldsm4(a1, aRow2 + au);
            uint32_t bfr[8][2];
#pragma unroll
            for (int p = 0; p < 4; p++) {
                uint32_t r[4];
                ldsm4(r, bRow + stageOff + p * 16 * 128 + bu);
                bfr[2 * p][0] = r[0]; bfr[2 * p][1] = r[2];
                bfr[2 * p + 1][0] = r[1]; bfr[2 * p + 1][1] = r[3];
            }
#pragma unroll
            for (int nt = 0; nt < 8; nt++) {
                mma16816(c[0][nt], a0, bfr[nt]);
                mma16816(c[1][nt], a1, bfr[nt]);
            }
        }

        if (cch == 3) {  // offset ko complete: fused BN + ReLU epilogue
            const size_t rbase = (size_t)ko * MT + (size_t)bx * BM + wm * 32 + (lane >> 2);
            const int colb = wn * 64 + (lane & 3) * 2;
#pragma unroll
            for (int nt = 0; nt < 8; nt++) {
                const int ch0 = colb + nt * 8;
                const float s0 = __ldg(&g_scale[ch0]), s1 = __ldg(&g_scale[ch0 + 1]);
                const float b0 = __ldg(&g_bias[ch0]),  b1 = __ldg(&g_bias[ch0 + 1]);
#pragma unroll
                for (int mt = 0; mt < 2; mt++) {
                    float y0 = fmaxf(fmaf(c[mt][nt][0], s0, b0), 0.f);
                    float y1 = fmaxf(fmaf(c[mt][nt][1], s1, b1), 0.f);
                    float y2 = fmaxf(fmaf(c[mt][nt][2], s0, b0), 0.f);
                    float y3 = fmaxf(fmaf(c[mt][nt][3], s1, b1), 0.f);
                    float* p0 = out + (rbase + mt * 16) * CO + ch0;
                    *(float2*)p0 = make_float2(y0, y1);
                    *(float2*)(p0 + 8 * CO) = make_float2(y2, y3);
                }
            }
#pragma unroll
            for (int mt = 0; mt < 2; mt++)
#pragma unroll
                for (int nt = 0; nt < 8; nt++)
#pragma unroll
                    for (int e = 0; e < 4; e++) c[mt][nt][e] = 0.f;
        }
    }
}

// ============================================================================
extern "C" void kernel_launch(void* const* d_in, const int* in_sizes, int n_in,
                              void* d_out, int out_size)
{
    const float* x     = (const float*)d_in[0];   // [65536,256]
    const float* W     = (const float*)d_in[1];   // [8,256,128]
    const float* gamma = (const float*)d_in[2];
    const float* beta  = (const float*)d_in[3];
    float* out = (float*)d_out;

    cudaFuncSetAttribute(gram_k,   cudaFuncAttributeMaxDynamicSharedMemorySize, 2 * GR_STAGE);
    cudaFuncSetAttribute(gemm_mma, cudaFuncAttributeMaxDynamicSharedMemorySize, SMEM_G);

    dim3 cgrid(MT / 64, KT / 64);
    convert_x<<<cgrid, 256>>>(x);
    convert_w<<<NOFF * CO, 256>>>(W);
    cs_reduce<<<KT, 256>>>();
    dim3 ggrid(GSPLIT, 4);
    gram_k<<<ggrid, 256, 2 * GR_STAGE>>>();
    gram_reduce<<<KT, 256>>>();
    stats_k<<<CO, 256>>>(W, gamma, beta);
    gemm_mma<<<MTILES, 256, SMEM_G>>>(out);
}